// round 1
// baseline (speedup 1.0000x reference)
#include <cuda_runtime.h>

// ---------------- configuration ----------------
#define CH      2048            // elements per chunk (per block), power of 2
#define LOG2CH  11
#define NT      128             // threads per block in pass 1/3
#define SEG     16              // CH / NT, power of 2
#define LOG2SEG 4
#define NW      4               // NT / 32 warps per block
#define K2T     1024            // threads in middle-scan kernel
#define MAXC    8192            // max number of chunks supported

// padded smem indexing: +1 word per 16 to kill stride-16 bank conflicts
#define PAD(i)  ((i) + ((i) >> 4))
#define CHP     (CH + (CH >> 4))

// scratch (no cudaMalloc allowed)
__device__ float g_chunkSum[MAXC][2];
__device__ float g_blockStart[MAXC][2];

// =====================================================================
// Pass 1: per-chunk affine summary  s_c  (x_end = A^CH * x_start + s_c)
// =====================================================================
__global__ __launch_bounds__(NT)
void k_pass1(const float* __restrict__ u,
             const float* __restrict__ WA, const float* __restrict__ bA,
             const float* __restrict__ WB, const float* __restrict__ bB,
             int T)
{
    __shared__ float s_u0[CHP];
    __shared__ float s_u1[CHP];
    __shared__ float s_aggV[NW][2];

    const int tid = threadIdx.x;
    const int c   = blockIdx.x;
    const long long base = (long long)c * CH;
    const float* __restrict__ u0 = u;
    const float* __restrict__ u1 = u + T;

    // ---- coalesced stage into padded shared memory ----
    if (base + CH <= (long long)T) {
        const float4* p0 = reinterpret_cast<const float4*>(u0 + base);
        const float4* p1 = reinterpret_cast<const float4*>(u1 + base);
        #pragma unroll
        for (int i = tid; i < CH / 4; i += NT) {
            float4 a = p0[i], b = p1[i];
            int j = i * 4, pj = PAD(j);       // j..j+3 stay inside one 16-group
            s_u0[pj] = a.x; s_u0[pj + 1] = a.y; s_u0[pj + 2] = a.z; s_u0[pj + 3] = a.w;
            s_u1[pj] = b.x; s_u1[pj + 1] = b.y; s_u1[pj + 2] = b.z; s_u1[pj + 3] = b.w;
        }
    } else {
        for (int i = tid; i < CH; i += NT) {
            long long t = base + i;
            s_u0[PAD(i)] = (t < T) ? u0[t] : 0.f;
            s_u1[PAD(i)] = (t < T) ? u1[t] : 0.f;
        }
    }

    const float A00 = WA[0], A01 = WA[1], A10 = WA[2], A11 = WA[3];
    const float B00 = WB[0], B01 = WB[1], B10 = WB[2], B11 = WB[3];
    const float bx = bA[0] + bB[0], by = bA[1] + bB[1];
    __syncthreads();

    // ---- per-thread serial fold of its SEG elements (start state = 0) ----
    float v0 = 0.f, v1 = 0.f;
    const int spBase = tid * SEG + tid;   // PAD(tid*SEG + j) = spBase + j  (j < 16)
    #pragma unroll
    for (int j = 0; j < SEG; j++) {
        float a = s_u0[spBase + j], b = s_u1[spBase + j];
        float d0 = B00 * a + B01 * b + bx;
        float d1 = B10 * a + B11 * b + by;
        float n0 = A00 * v0 + A01 * v1 + d0;
        float n1 = A10 * v0 + A11 * v1 + d1;
        v0 = n0; v1 = n1;
    }

    // Q = A^SEG (by squaring)
    float Q00 = A00, Q01 = A01, Q10 = A10, Q11 = A11;
    #pragma unroll
    for (int k = 0; k < LOG2SEG; k++) {
        float t00 = Q00 * Q00 + Q01 * Q10, t01 = Q00 * Q01 + Q01 * Q11;
        float t10 = Q10 * Q00 + Q11 * Q10, t11 = Q10 * Q01 + Q11 * Q11;
        Q00 = t00; Q01 = t01; Q10 = t10; Q11 = t11;
    }

    // ---- v-only Kogge-Stone warp scan (matrices are known powers of A) ----
    const unsigned FULL = 0xffffffffu;
    const int lane = tid & 31;
    #pragma unroll
    for (int off = 1; off < 32; off <<= 1) {
        float pv0 = __shfl_up_sync(FULL, v0, off);
        float pv1 = __shfl_up_sync(FULL, v1, off);
        if (lane >= off) {
            float n0 = Q00 * pv0 + Q01 * pv1 + v0;
            float n1 = Q10 * pv0 + Q11 * pv1 + v1;
            v0 = n0; v1 = n1;
        }
        float t00 = Q00 * Q00 + Q01 * Q10, t01 = Q00 * Q01 + Q01 * Q11;
        float t10 = Q10 * Q00 + Q11 * Q10, t11 = Q10 * Q01 + Q11 * Q11;
        Q00 = t00; Q01 = t01; Q10 = t10; Q11 = t11;
    }
    // after loop: Q = A^(SEG*32) = A^512  (per-warp span)

    const int w = tid >> 5;
    if (lane == 31) { s_aggV[w][0] = v0; s_aggV[w][1] = v1; }
    __syncthreads();

    if (tid == 0) {
        float f0 = s_aggV[0][0], f1 = s_aggV[0][1];
        #pragma unroll
        for (int ww = 1; ww < NW; ww++) {
            float t0 = Q00 * f0 + Q01 * f1 + s_aggV[ww][0];
            float t1 = Q10 * f0 + Q11 * f1 + s_aggV[ww][1];
            f0 = t0; f1 = t1;
        }
        g_chunkSum[c][0] = f0;
        g_chunkSum[c][1] = f1;
    }
}

// =====================================================================
// Pass 2: scan chunk summaries -> exact state at each chunk start
// =====================================================================
__global__ __launch_bounds__(K2T)
void k_pass2(const float* __restrict__ x0in, const float* __restrict__ WA, int C)
{
    __shared__ float sM[K2T][4];
    __shared__ float sV[K2T][2];
    __shared__ float sCarry[6];

    const int tid = threadIdx.x;
    const float A00 = WA[0], A01 = WA[1], A10 = WA[2], A11 = WA[3];

    // P = A^CH
    float P00 = A00, P01 = A01, P10 = A10, P11 = A11;
    #pragma unroll
    for (int k = 0; k < LOG2CH; k++) {
        float t00 = P00 * P00 + P01 * P10, t01 = P00 * P01 + P01 * P11;
        float t10 = P10 * P00 + P11 * P10, t11 = P10 * P01 + P11 * P11;
        P00 = t00; P01 = t01; P10 = t10; P11 = t11;
    }

    const float X0 = x0in[0], X1 = x0in[1];
    // running carry (affine map from x0 to state after last processed chunk)
    float C00 = 1.f, C01 = 0.f, C10 = 0.f, C11 = 1.f, Cv0 = 0.f, Cv1 = 0.f;

    for (int tb = 0; tb < C; tb += K2T) {
        const int c = tb + tid;
        float M00, M01, M10, M11, v0, v1;
        if (c < C) {
            M00 = P00; M01 = P01; M10 = P10; M11 = P11;
            v0 = g_chunkSum[c][0]; v1 = g_chunkSum[c][1];
        } else {
            M00 = 1.f; M01 = 0.f; M10 = 0.f; M11 = 1.f; v0 = 0.f; v1 = 0.f;
        }
        sM[tid][0] = M00; sM[tid][1] = M01; sM[tid][2] = M10; sM[tid][3] = M11;
        sV[tid][0] = v0;  sV[tid][1] = v1;
        __syncthreads();

        for (int off = 1; off < K2T; off <<= 1) {
            float pm00, pm01, pm10, pm11, pv0, pv1;
            const bool act = (tid >= off);
            if (act) {
                pm00 = sM[tid - off][0]; pm01 = sM[tid - off][1];
                pm10 = sM[tid - off][2]; pm11 = sM[tid - off][3];
                pv0  = sV[tid - off][0]; pv1  = sV[tid - off][1];
            }
            __syncthreads();
            if (act) {
                float nv0 = M00 * pv0 + M01 * pv1 + v0;
                float nv1 = M10 * pv0 + M11 * pv1 + v1;
                float t00 = M00 * pm00 + M01 * pm10, t01 = M00 * pm01 + M01 * pm11;
                float t10 = M10 * pm00 + M11 * pm10, t11 = M10 * pm01 + M11 * pm11;
                M00 = t00; M01 = t01; M10 = t10; M11 = t11; v0 = nv0; v1 = nv1;
                sM[tid][0] = M00; sM[tid][1] = M01; sM[tid][2] = M10; sM[tid][3] = M11;
                sV[tid][0] = v0;  sV[tid][1] = v1;
            }
            __syncthreads();
        }

        // global inclusive G_c = local_incl ∘ carry
        float G00 = M00 * C00 + M01 * C10;
        float G01 = M00 * C01 + M01 * C11;
        float G10 = M10 * C00 + M11 * C10;
        float G11 = M10 * C01 + M11 * C11;
        float Gv0 = M00 * Cv0 + M01 * Cv1 + v0;
        float Gv1 = M10 * Cv0 + M11 * Cv1 + v1;

        if (tid == 0 && tb == 0) { g_blockStart[0][0] = X0; g_blockStart[0][1] = X1; }
        if (c < C && c + 1 < C) {
            g_blockStart[c + 1][0] = G00 * X0 + G01 * X1 + Gv0;
            g_blockStart[c + 1][1] = G10 * X0 + G11 * X1 + Gv1;
        }

        const int lastLocal = min(C - tb, K2T) - 1;
        if (tid == lastLocal) {
            sCarry[0] = G00; sCarry[1] = G01; sCarry[2] = G10; sCarry[3] = G11;
            sCarry[4] = Gv0; sCarry[5] = Gv1;
        }
        __syncthreads();
        C00 = sCarry[0]; C01 = sCarry[1]; C10 = sCarry[2]; C11 = sCarry[3];
        Cv0 = sCarry[4]; Cv1 = sCarry[5];
        __syncthreads();
    }
}

// =====================================================================
// Pass 3: replay each chunk from its exact start state, write outputs
// =====================================================================
__global__ __launch_bounds__(NT)
void k_pass3(const float* __restrict__ u, const float* __restrict__ td,
             const float* __restrict__ WA, const float* __restrict__ bA,
             const float* __restrict__ WB, const float* __restrict__ bB,
             float* __restrict__ out, int T)
{
    __shared__ float s_u0[CHP];
    __shared__ float s_u1[CHP];
    __shared__ float s_td[CHP];
    __shared__ float s_out[2 * CHP];     // element t at words 2*PAD(t), 2*PAD(t)+1
    __shared__ float s_aggV[NW][2];
    __shared__ float s_ws[NW][2];

    const int tid = threadIdx.x;
    const int c   = blockIdx.x;
    const long long base = (long long)c * CH;
    const float* __restrict__ u0 = u;
    const float* __restrict__ u1 = u + T;

    if (base + CH <= (long long)T) {
        const float4* p0 = reinterpret_cast<const float4*>(u0 + base);
        const float4* p1 = reinterpret_cast<const float4*>(u1 + base);
        const float4* pt = reinterpret_cast<const float4*>(td + base);
        #pragma unroll
        for (int i = tid; i < CH / 4; i += NT) {
            float4 a = p0[i], b = p1[i], d = pt[i];
            int j = i * 4, pj = PAD(j);
            s_u0[pj] = a.x; s_u0[pj + 1] = a.y; s_u0[pj + 2] = a.z; s_u0[pj + 3] = a.w;
            s_u1[pj] = b.x; s_u1[pj + 1] = b.y; s_u1[pj + 2] = b.z; s_u1[pj + 3] = b.w;
            s_td[pj] = d.x; s_td[pj + 1] = d.y; s_td[pj + 2] = d.z; s_td[pj + 3] = d.w;
        }
    } else {
        for (int i = tid; i < CH; i += NT) {
            long long t = base + i;
            s_u0[PAD(i)] = (t < T) ? u0[t] : 0.f;
            s_u1[PAD(i)] = (t < T) ? u1[t] : 0.f;
            s_td[PAD(i)] = (t < T) ? td[t] : 0.f;
        }
    }

    const float A00 = WA[0], A01 = WA[1], A10 = WA[2], A11 = WA[3];
    const float B00 = WB[0], B01 = WB[1], B10 = WB[2], B11 = WB[3];
    const float bx = bA[0] + bB[0], by = bA[1] + bB[1];
    __syncthreads();

    // per-thread segment summary (same as pass 1)
    float v0 = 0.f, v1 = 0.f;
    const int spBase = tid * SEG + tid;
    #pragma unroll
    for (int j = 0; j < SEG; j++) {
        float a = s_u0[spBase + j], b = s_u1[spBase + j];
        float d0 = B00 * a + B01 * b + bx;
        float d1 = B10 * a + B11 * b + by;
        float n0 = A00 * v0 + A01 * v1 + d0;
        float n1 = A10 * v0 + A11 * v1 + d1;
        v0 = n0; v1 = n1;
    }

    float Q00 = A00, Q01 = A01, Q10 = A10, Q11 = A11;   // A^(2^k * SEG) ladder
    #pragma unroll
    for (int k = 0; k < LOG2SEG; k++) {
        float t00 = Q00 * Q00 + Q01 * Q10, t01 = Q00 * Q01 + Q01 * Q11;
        float t10 = Q10 * Q00 + Q11 * Q10, t11 = Q10 * Q01 + Q11 * Q11;
        Q00 = t00; Q01 = t01; Q10 = t10; Q11 = t11;
    }
    // now Q = A^SEG

    const unsigned FULL = 0xffffffffu;
    const int lane = tid & 31;
    // E accumulates A^(SEG*lane) via binary expansion of lane
    float E00 = 1.f, E01 = 0.f, E10 = 0.f, E11 = 0.f;
    float E11i = 1.f; // E = I initially
    E11 = E11i;
    #pragma unroll
    for (int off = 1; off < 32; off <<= 1) {
        float pv0 = __shfl_up_sync(FULL, v0, off);
        float pv1 = __shfl_up_sync(FULL, v1, off);
        if (lane >= off) {
            float n0 = Q00 * pv0 + Q01 * pv1 + v0;
            float n1 = Q10 * pv0 + Q11 * pv1 + v1;
            v0 = n0; v1 = n1;
        }
        if (lane & off) {   // E = Q * E  (powers of A commute)
            float e00 = Q00 * E00 + Q01 * E10, e01 = Q00 * E01 + Q01 * E11;
            float e10 = Q10 * E00 + Q11 * E10, e11 = Q10 * E01 + Q11 * E11;
            E00 = e00; E01 = e01; E10 = e10; E11 = e11;
        }
        float t00 = Q00 * Q00 + Q01 * Q10, t01 = Q00 * Q01 + Q01 * Q11;
        float t10 = Q10 * Q00 + Q11 * Q10, t11 = Q10 * Q01 + Q11 * Q11;
        Q00 = t00; Q01 = t01; Q10 = t10; Q11 = t11;
    }
    // Q = A^512 (warp span)

    // exclusive v within warp
    float ev0 = __shfl_up_sync(FULL, v0, 1);
    float ev1 = __shfl_up_sync(FULL, v1, 1);
    if (lane == 0) { ev0 = 0.f; ev1 = 0.f; }

    const int w = tid >> 5;
    if (lane == 31) { s_aggV[w][0] = v0; s_aggV[w][1] = v1; }
    __syncthreads();

    if (tid == 0) {
        float w0 = g_blockStart[c][0], w1 = g_blockStart[c][1];
        s_ws[0][0] = w0; s_ws[0][1] = w1;
        #pragma unroll
        for (int ww = 1; ww < NW; ww++) {
            float t0 = Q00 * w0 + Q01 * w1 + s_aggV[ww - 1][0];
            float t1 = Q10 * w0 + Q11 * w1 + s_aggV[ww - 1][1];
            w0 = t0; w1 = t1;
            s_ws[ww][0] = w0; s_ws[ww][1] = w1;
        }
    }
    __syncthreads();

    const float ws0 = s_ws[w][0], ws1 = s_ws[w][1];
    float xp0 = E00 * ws0 + E01 * ws1 + ev0;
    float xp1 = E10 * ws0 + E11 * ws1 + ev1;

    // ---- replay segment, produce outputs into padded smem ----
    #pragma unroll
    for (int j = 0; j < SEG; j++) {
        float a  = s_u0[spBase + j];
        float b  = s_u1[spBase + j];
        float dt = s_td[spBase + j];
        float d0 = B00 * a + B01 * b + bx;
        float d1 = B10 * a + B11 * b + by;
        float n0 = A00 * xp0 + A01 * xp1 + d0;
        float n1 = A10 * xp0 + A11 * xp1 + d1;
        float cc = a * dt;
        float sn, cs;
        sincosf(b, &sn, &cs);
        s_out[2 * (spBase + j)]     = xp0 + cc * cs - n0;
        s_out[2 * (spBase + j) + 1] = xp1 + cc * sn - n1;
        xp0 = n0; xp1 = n1;
    }
    __syncthreads();

    // ---- coalesced writeout ----
    if (base + CH <= (long long)T) {
        float4* o4 = reinterpret_cast<float4*>(out + 2 * base);
        #pragma unroll
        for (int i = tid; i < CH / 2; i += NT) {
            int t = i * 2;                 // t even -> t, t+1 in same 16-group
            int p = PAD(t);
            o4[i] = make_float4(s_out[2 * p], s_out[2 * p + 1],
                                s_out[2 * p + 2], s_out[2 * p + 3]);
        }
    } else {
        for (int i = tid; i < CH; i += NT) {
            long long t = base + i;
            if (t < T) {
                out[2 * t]     = s_out[2 * PAD(i)];
                out[2 * t + 1] = s_out[2 * PAD(i) + 1];
            }
        }
    }
}

// =====================================================================
extern "C" void kernel_launch(void* const* d_in, const int* in_sizes, int n_in,
                              void* d_out, int out_size)
{
    const float* x0 = (const float*)d_in[0];
    const float* u  = (const float*)d_in[1];
    const float* td = (const float*)d_in[2];
    const float* WA = (const float*)d_in[3];
    const float* bA = (const float*)d_in[4];
    const float* WB = (const float*)d_in[5];
    const float* bB = (const float*)d_in[6];
    float* out = (float*)d_out;

    const int T = in_sizes[2];                // timedelta length
    const int C = (T + CH - 1) / CH;          // number of chunks (2048 for T=4M)

    k_pass1<<<C, NT>>>(u, WA, bA, WB, bB, T);
    k_pass2<<<1, K2T>>>(x0, WA, C);
    k_pass3<<<C, NT>>>(u, td, WA, bA, WB, bB, out, T);
}

// round 2
// speedup vs baseline: 1.2717x; 1.2717x over previous
#include <cuda_runtime.h>

// ---------------- configuration ----------------
#define CH      2048            // elements per chunk (per block), power of 2
#define LOG2CH  11
#define NT      128             // threads per block in pass 1/3
#define SEG     16              // CH / NT
#define LOG2SEG 4
#define NW      4               // NT / 32
#define K2T     1024            // threads in middle-scan kernel
#define MAXC    8192

// padded smem indexing: +1 word per 16 (pass3 output staging)
#define PAD(i)  ((i) + ((i) >> 4))
#define CHP     (CH + (CH >> 4))

#define FULLM 0xffffffffu

// scratch (no cudaMalloc allowed)
__device__ float2 g_chunkSum[MAXC];
__device__ float2 g_blockStart[MAXC];
__device__ float2 g_ev[MAXC * NT];      // per-thread chunk-relative exclusive prefix

// 2x2 matrix square helper (powers of A commute; all FMA-able)
#define MSQR(Q00,Q01,Q10,Q11) do {                                   \
    float t00 = Q00*Q00 + Q01*Q10, t01 = Q00*Q01 + Q01*Q11;          \
    float t10 = Q10*Q00 + Q11*Q10, t11 = Q10*Q01 + Q11*Q11;          \
    Q00 = t00; Q01 = t01; Q10 = t10; Q11 = t11; } while (0)

// E = W * E
#define MMUL_INTO(E00,E01,E10,E11,W00,W01,W10,W11) do {              \
    float e00 = W00*E00 + W01*E10, e01 = W00*E01 + W01*E11;          \
    float e10 = W10*E00 + W11*E10, e11 = W10*E01 + W11*E11;          \
    E00 = e00; E01 = e01; E10 = e10; E11 = e11; } while (0)

// =====================================================================
// Pass 1: per-chunk summary + per-thread exclusive prefixes (register-only)
// =====================================================================
__global__ __launch_bounds__(NT)
void k_pass1(const float* __restrict__ u,
             const float* __restrict__ WA, const float* __restrict__ bA,
             const float* __restrict__ WB, const float* __restrict__ bB,
             int T)
{
    __shared__ float s_agg[NW][2];
    __shared__ float s_wb[NW][2];

    const int tid = threadIdx.x, c = blockIdx.x;
    const int lane = tid & 31, w = tid >> 5;
    const long long cbase = (long long)c * CH;
    const long long tbase = cbase + (long long)tid * SEG;

    const float A00 = WA[0], A01 = WA[1], A10 = WA[2], A11 = WA[3];
    const float B00 = WB[0], B01 = WB[1], B10 = WB[2], B11 = WB[3];
    const float bx = bA[0] + bB[0], by = bA[1] + bB[1];

    // ---- per-thread serial fold of SEG contiguous elements (zero init) ----
    float v0 = 0.f, v1 = 0.f;
    if (cbase + CH <= (long long)T) {
        const float4* p0 = reinterpret_cast<const float4*>(u + tbase);
        const float4* p1 = reinterpret_cast<const float4*>(u + (long long)T + tbase);
        float4 ua[4], ub[4];
        #pragma unroll
        for (int g = 0; g < 4; g++) { ua[g] = p0[g]; ub[g] = p1[g]; }
        const float* af = reinterpret_cast<const float*>(ua);
        const float* bf = reinterpret_cast<const float*>(ub);
        #pragma unroll
        for (int j = 0; j < SEG; j++) {
            float a = af[j], b = bf[j];
            float d0 = B00 * a + B01 * b + bx;
            float d1 = B10 * a + B11 * b + by;
            float n0 = A00 * v0 + A01 * v1 + d0;
            float n1 = A10 * v0 + A11 * v1 + d1;
            v0 = n0; v1 = n1;
        }
    } else {
        #pragma unroll
        for (int j = 0; j < SEG; j++) {
            long long t = tbase + j;
            float a = (t < T) ? u[t] : 0.f;
            float b = (t < T) ? u[(long long)T + t] : 0.f;
            float d0 = B00 * a + B01 * b + bx;
            float d1 = B10 * a + B11 * b + by;
            float n0 = A00 * v0 + A01 * v1 + d0;
            float n1 = A10 * v0 + A11 * v1 + d1;
            v0 = n0; v1 = n1;
        }
    }

    // Q = A^SEG
    float Q00 = A00, Q01 = A01, Q10 = A10, Q11 = A11;
    #pragma unroll
    for (int k = 0; k < LOG2SEG; k++) MSQR(Q00, Q01, Q10, Q11);

    // ---- warp KS v-scan + E = A^(SEG*lane) ladder ----
    float E00 = 1.f, E01 = 0.f, E10 = 0.f, E11 = 1.f;
    #pragma unroll
    for (int off = 1; off < 32; off <<= 1) {
        float pv0 = __shfl_up_sync(FULLM, v0, off);
        float pv1 = __shfl_up_sync(FULLM, v1, off);
        if (lane >= off) {
            float n0 = Q00 * pv0 + Q01 * pv1 + v0;
            float n1 = Q10 * pv0 + Q11 * pv1 + v1;
            v0 = n0; v1 = n1;
        }
        if (lane & off) MMUL_INTO(E00, E01, E10, E11, Q00, Q01, Q10, Q11);
        MSQR(Q00, Q01, Q10, Q11);
    }
    // Q = A^512 (warp span)

    float ev0 = __shfl_up_sync(FULLM, v0, 1);
    float ev1 = __shfl_up_sync(FULLM, v1, 1);
    if (lane == 0) { ev0 = 0.f; ev1 = 0.f; }

    if (lane == 31) { s_agg[w][0] = v0; s_agg[w][1] = v1; }
    __syncthreads();

    if (tid == 0) {
        float w0 = 0.f, w1 = 0.f;
        #pragma unroll
        for (int ww = 0; ww < NW; ww++) {
            s_wb[ww][0] = w0; s_wb[ww][1] = w1;
            float t0 = s_agg[ww][0] + Q00 * w0 + Q01 * w1;
            float t1 = s_agg[ww][1] + Q10 * w0 + Q11 * w1;
            w0 = t0; w1 = t1;
        }
        g_chunkSum[c] = make_float2(w0, w1);
    }
    __syncthreads();

    const float wb0 = s_wb[w][0], wb1 = s_wb[w][1];
    g_ev[c * NT + tid] = make_float2(ev0 + E00 * wb0 + E01 * wb1,
                                     ev1 + E10 * wb0 + E11 * wb1);
}

// =====================================================================
// Pass 2: shuffle-based scan of chunk summaries -> absolute chunk starts
// =====================================================================
__global__ __launch_bounds__(K2T)
void k_pass2(const float* __restrict__ x0in, const float* __restrict__ WA, int C)
{
    __shared__ float s_agg[32][2];
    __shared__ float s_wb[32][2];

    const int tid = threadIdx.x, lane = tid & 31, w = tid >> 5;
    const float A00 = WA[0], A01 = WA[1], A10 = WA[2], A11 = WA[3];

    // P = A^CH
    float P00 = A00, P01 = A01, P10 = A10, P11 = A11;
    #pragma unroll
    for (int k = 0; k < LOG2CH; k++) MSQR(P00, P01, P10, P11);

    const int s = (C + K2T - 1) / K2T;
    const int j0 = tid * s;

    // local fold over s chunks (virtual pad: v=0 chunks beyond C — harmless)
    float v0 = 0.f, v1 = 0.f;
    for (int k = 0; k < s; k++) {
        int j = j0 + k;
        float cv0 = 0.f, cv1 = 0.f;
        if (j < C) { float2 cs = g_chunkSum[j]; cv0 = cs.x; cv1 = cs.y; }
        float n0 = P00 * v0 + P01 * v1 + cv0;
        float n1 = P10 * v0 + P11 * v1 + cv1;
        v0 = n0; v1 = n1;
    }

    // Qs = P^s (binary power)
    float Qs00 = 1.f, Qs01 = 0.f, Qs10 = 0.f, Qs11 = 1.f;
    {
        float W00 = P00, W01 = P01, W10 = P10, W11 = P11;
        int e = s;
        while (e) {
            if (e & 1) MMUL_INTO(Qs00, Qs01, Qs10, Qs11, W00, W01, W10, W11);
            MSQR(W00, W01, W10, W11);
            e >>= 1;
        }
    }

    // warp KS + E = Qs^lane ladder
    float Q00 = Qs00, Q01 = Qs01, Q10 = Qs10, Q11 = Qs11;
    float E00 = 1.f, E01 = 0.f, E10 = 0.f, E11 = 1.f;
    #pragma unroll
    for (int off = 1; off < 32; off <<= 1) {
        float pv0 = __shfl_up_sync(FULLM, v0, off);
        float pv1 = __shfl_up_sync(FULLM, v1, off);
        if (lane >= off) {
            float n0 = Q00 * pv0 + Q01 * pv1 + v0;
            float n1 = Q10 * pv0 + Q11 * pv1 + v1;
            v0 = n0; v1 = n1;
        }
        if (lane & off) MMUL_INTO(E00, E01, E10, E11, Q00, Q01, Q10, Q11);
        MSQR(Q00, Q01, Q10, Q11);
    }
    // Q = Qs^32 (warp span)

    float ev0 = __shfl_up_sync(FULLM, v0, 1);
    float ev1 = __shfl_up_sync(FULLM, v1, 1);
    if (lane == 0) { ev0 = 0.f; ev1 = 0.f; }

    if (lane == 31) { s_agg[w][0] = v0; s_agg[w][1] = v1; }
    __syncthreads();

    if (w == 0) {
        // warp 0 scans the 32 warp aggregates (matrix = warp-span Q)
        float a0 = s_agg[lane][0], a1 = s_agg[lane][1];
        float R00 = Q00, R01 = Q01, R10 = Q10, R11 = Q11;
        #pragma unroll
        for (int off = 1; off < 32; off <<= 1) {
            float pa0 = __shfl_up_sync(FULLM, a0, off);
            float pa1 = __shfl_up_sync(FULLM, a1, off);
            if (lane >= off) {
                float n0 = R00 * pa0 + R01 * pa1 + a0;
                float n1 = R10 * pa0 + R11 * pa1 + a1;
                a0 = n0; a1 = n1;
            }
            MSQR(R00, R01, R10, R11);
        }
        float wb0 = __shfl_up_sync(FULLM, a0, 1);
        float wb1 = __shfl_up_sync(FULLM, a1, 1);
        if (lane == 0) { wb0 = 0.f; wb1 = 0.f; }
        s_wb[lane][0] = wb0; s_wb[lane][1] = wb1;
    }
    __syncthreads();

    const float wb0 = s_wb[w][0], wb1 = s_wb[w][1];
    float pe0 = ev0 + E00 * wb0 + E01 * wb1;   // relative exclusive prefix
    float pe1 = ev1 + E10 * wb0 + E11 * wb1;

    // M = Qs^tid (10-bit ladder)
    float M00 = 1.f, M01 = 0.f, M10 = 0.f, M11 = 1.f;
    {
        float W00 = Qs00, W01 = Qs01, W10 = Qs10, W11 = Qs11;
        #pragma unroll
        for (int bit = 0; bit < 10; bit++) {
            if (tid & (1 << bit)) MMUL_INTO(M00, M01, M10, M11, W00, W01, W10, W11);
            MSQR(W00, W01, W10, W11);
        }
    }

    const float X0 = x0in[0], X1 = x0in[1];
    float x0v = M00 * X0 + M01 * X1 + pe0;     // absolute state before thread's chunks
    float x1v = M10 * X0 + M11 * X1 + pe1;

    if (tid == 0) g_blockStart[0] = make_float2(X0, X1);
    for (int k = 0; k < s; k++) {
        int j = j0 + k;
        if (j < C) {
            float2 cs = g_chunkSum[j];
            float n0 = P00 * x0v + P01 * x1v + cs.x;
            float n1 = P10 * x0v + P11 * x1v + cs.y;
            x0v = n0; x1v = n1;
            if (j + 1 < C) g_blockStart[j + 1] = make_float2(x0v, x1v);
        }
    }
}

// =====================================================================
// Pass 3: pure stream — no scan. Start state from blockStart + ev + ladder.
// =====================================================================
__global__ __launch_bounds__(NT)
void k_pass3(const float* __restrict__ u, const float* __restrict__ td,
             const float* __restrict__ WA, const float* __restrict__ bA,
             const float* __restrict__ WB, const float* __restrict__ bB,
             float* __restrict__ out, int T)
{
    __shared__ float s_out[2 * CHP];

    const int tid = threadIdx.x, c = blockIdx.x;
    const long long cbase = (long long)c * CH;
    const long long tbase = cbase + (long long)tid * SEG;

    const float A00 = WA[0], A01 = WA[1], A10 = WA[2], A11 = WA[3];
    const float B00 = WB[0], B01 = WB[1], B10 = WB[2], B11 = WB[3];
    const float bx = bA[0] + bB[0], by = bA[1] + bB[1];

    // E = A^(SEG * tid): 4 squarings to A^SEG, then 7-bit ladder over tid
    float W00 = A00, W01 = A01, W10 = A10, W11 = A11;
    #pragma unroll
    for (int k = 0; k < LOG2SEG; k++) MSQR(W00, W01, W10, W11);
    float E00 = 1.f, E01 = 0.f, E10 = 0.f, E11 = 1.f;
    #pragma unroll
    for (int bit = 0; bit < 7; bit++) {
        if (tid & (1 << bit)) MMUL_INTO(E00, E01, E10, E11, W00, W01, W10, W11);
        MSQR(W00, W01, W10, W11);
    }

    const float2 bs = g_blockStart[c];
    const float2 ev = g_ev[c * NT + tid];
    float xp0 = E00 * bs.x + E01 * bs.y + ev.x;
    float xp1 = E10 * bs.x + E11 * bs.y + ev.y;

    const int spBase = tid * SEG + tid;   // padded base (stride 17)

    if (cbase + CH <= (long long)T) {
        const float4* p0 = reinterpret_cast<const float4*>(u + tbase);
        const float4* p1 = reinterpret_cast<const float4*>(u + (long long)T + tbase);
        const float4* pt = reinterpret_cast<const float4*>(td + tbase);
        float4 ua[4], ub[4], ut[4];
        #pragma unroll
        for (int g = 0; g < 4; g++) { ua[g] = p0[g]; ub[g] = p1[g]; ut[g] = pt[g]; }
        const float* af = reinterpret_cast<const float*>(ua);
        const float* bf = reinterpret_cast<const float*>(ub);
        const float* df = reinterpret_cast<const float*>(ut);

        #pragma unroll
        for (int j = 0; j < SEG; j++) {
            float a = af[j], b = bf[j], dt = df[j];
            float d0 = B00 * a + B01 * b + bx;
            float d1 = B10 * a + B11 * b + by;
            float n0 = A00 * xp0 + A01 * xp1 + d0;
            float n1 = A10 * xp0 + A11 * xp1 + d1;
            float cc = a * dt;
            float sn, cs;
            __sincosf(b, &sn, &cs);
            s_out[2 * (spBase + j)]     = xp0 + cc * cs - n0;
            s_out[2 * (spBase + j) + 1] = xp1 + cc * sn - n1;
            xp0 = n0; xp1 = n1;
        }
        __syncthreads();

        float4* o4 = reinterpret_cast<float4*>(out + 2 * cbase);
        #pragma unroll
        for (int i = tid; i < CH / 2; i += NT) {
            int t = i * 2, p = PAD(t);
            o4[i] = make_float4(s_out[2 * p], s_out[2 * p + 1],
                                s_out[2 * p + 2], s_out[2 * p + 3]);
        }
    } else {
        for (int j = 0; j < SEG; j++) {
            long long t = tbase + j;
            float a  = (t < T) ? u[t] : 0.f;
            float b  = (t < T) ? u[(long long)T + t] : 0.f;
            float dt = (t < T) ? td[t] : 0.f;
            float d0 = B00 * a + B01 * b + bx;
            float d1 = B10 * a + B11 * b + by;
            float n0 = A00 * xp0 + A01 * xp1 + d0;
            float n1 = A10 * xp0 + A11 * xp1 + d1;
            float cc = a * dt;
            float sn, cs;
            __sincosf(b, &sn, &cs);
            if (t < T) {
                out[2 * t]     = xp0 + cc * cs - n0;
                out[2 * t + 1] = xp1 + cc * sn - n1;
            }
            xp0 = n0; xp1 = n1;
        }
    }
}

// =====================================================================
extern "C" void kernel_launch(void* const* d_in, const int* in_sizes, int n_in,
                              void* d_out, int out_size)
{
    const float* x0 = (const float*)d_in[0];
    const float* u  = (const float*)d_in[1];
    const float* td = (const float*)d_in[2];
    const float* WA = (const float*)d_in[3];
    const float* bA = (const float*)d_in[4];
    const float* WB = (const float*)d_in[5];
    const float* bB = (const float*)d_in[6];
    float* out = (float*)d_out;

    const int T = in_sizes[2];
    const int C = (T + CH - 1) / CH;

    k_pass1<<<C, NT>>>(u, WA, bA, WB, bB, T);
    k_pass2<<<1, K2T>>>(x0, WA, C);
    k_pass3<<<C, NT>>>(u, td, WA, bA, WB, bB, out, T);
}